// round 10
// baseline (speedup 1.0000x reference)
#include <cuda_runtime.h>
#include <cuda_bf16.h>
#include <math.h>
#include <stdint.h>

// ---------------------------------------------------------------------------
// CrossScaleNonLocalAttention  (B=8, H=W=64, C=64, CI=32, SCALE=4, PATCH=3)
//
// R7: both GEMMs on mma.sync.m16n8k16 bf16 with hi/lo split (3 products ~
// fp32 precision). k_scores_mma fuses softmax. Producers emit bf16 hi/lo
// operands (theta from k_theta_g, phin from k_phin, Ap from k_aprime, Gt
// transposed from k_theta_g).
// ---------------------------------------------------------------------------

#define NB 8

__device__ float d_phi[NB][18][18][32];             // zero-padded border
__device__ float d_attn[NB][4096][256];
__device__ __nv_bfloat16 d_th_h[NB][66][66][32];    // theta hi/lo, padded
__device__ __nv_bfloat16 d_th_l[NB][66][66][32];
__device__ __nv_bfloat16 d_phin_h[NB][256][288];    // phin[n][k] hi/lo
__device__ __nv_bfloat16 d_phin_l[NB][256][288];
__device__ __nv_bfloat16 d_Ap_h[NB][4096][256];     // A' hi/lo split
__device__ __nv_bfloat16 d_Ap_l[NB][4096][256];
__device__ __nv_bfloat16 d_Gt_h[NB][1024][256];     // Gt[n][k] hi/lo split
__device__ __nv_bfloat16 d_Gt_l[NB][1024][256];

// ---- mma.sync helpers ------------------------------------------------------
__device__ __forceinline__ uint32_t smem_to_u32(const void* p) {
    uint32_t a;
    asm("{ .reg .u64 tmp; cvta.to.shared.u64 tmp, %1; cvt.u32.u64 %0, tmp; }"
        : "=r"(a) : "l"(p));
    return a;
}
__device__ __forceinline__ void ldsm_x4(uint32_t* r, uint32_t addr) {
    asm volatile("ldmatrix.sync.aligned.m8n8.x4.shared.b16 {%0,%1,%2,%3}, [%4];"
                 : "=r"(r[0]), "=r"(r[1]), "=r"(r[2]), "=r"(r[3]) : "r"(addr));
}
__device__ __forceinline__ void mma_bf16(float* d, const uint32_t* a, const uint32_t* b) {
    asm volatile(
        "mma.sync.aligned.m16n8k16.row.col.f32.bf16.bf16.f32 "
        "{%0,%1,%2,%3}, {%4,%5,%6,%7}, {%8,%9}, {%0,%1,%2,%3};"
        : "+f"(d[0]), "+f"(d[1]), "+f"(d[2]), "+f"(d[3])
        : "r"(a[0]), "r"(a[1]), "r"(a[2]), "r"(a[3]), "r"(b[0]), "r"(b[1]));
}
// conflict-free XOR swizzle for 64B rows of 16B segments
#define SW64(row, colb) ((row) * 64 + (((((colb) >> 4) ^ (((row) >> 1) & 3))) << 4))

// ---------------------------------------------------------------------------
// Kernel 1: theta (64->32) and g (64->64) 1x1 conv + PReLU, fused.
// theta stored bf16 hi/lo padded [66][66][32]; g transposed to Gt[n][k] hi/lo.
// ---------------------------------------------------------------------------
__global__ __launch_bounds__(256) void k_theta_g(
    const float* __restrict__ x,
    const float* __restrict__ tw, const float* __restrict__ tb, const float* __restrict__ ta,
    const float* __restrict__ gw, const float* __restrict__ gb, const float* __restrict__ ga)
{
    int b = blockIdx.x >> 6, h = blockIdx.x & 63;
    __shared__ float xs[64 * 64];
    __shared__ float tws[64 * 32];
    __shared__ float gws[64 * 64];
    __shared__ float tbs[32], tas[32], gbs[64], gas[64];
    int t = threadIdx.x;
    for (int i = t; i < 64 * 32; i += 256) tws[i] = tw[i];
    for (int i = t; i < 64 * 64; i += 256) gws[i] = gw[i];
    if (t < 32) { tbs[t] = tb[t]; tas[t] = ta[t]; }
    if (t < 64) { gbs[t] = gb[t]; gas[t] = ga[t]; }
    const float* xrow = x + ((size_t)(b * 4096 + h * 64)) * 64;
    for (int i = t * 4; i < 4096; i += 1024)
        *(float4*)&xs[i] = *(const float4*)&xrow[i];
    __syncthreads();

    int px = t >> 2, l4 = t & 3;
    // theta: 8 outputs per thread -> bf16 hi/lo
    {
        float acc[8];
        int d0 = l4 * 8;
        #pragma unroll
        for (int j = 0; j < 8; j++) acc[j] = tbs[d0 + j];
        #pragma unroll 8
        for (int c = 0; c < 64; c++) {
            float xv = xs[px * 64 + c];
            #pragma unroll
            for (int j = 0; j < 8; j++) acc[j] = fmaf(xv, tws[c * 32 + d0 + j], acc[j]);
        }
        __nv_bfloat16 th[8], tl[8];
        #pragma unroll
        for (int j = 0; j < 8; j++) {
            float v = acc[j];
            v = v >= 0.f ? v : tas[d0 + j] * v;
            __nv_bfloat16 hb = __float2bfloat16(v);
            th[j] = hb;
            tl[j] = __float2bfloat16(v - __bfloat162float(hb));
        }
        *(uint4*)&d_th_h[b][h + 1][px + 1][d0] = *(uint4*)th;
        *(uint4*)&d_th_l[b][h + 1][px + 1][d0] = *(uint4*)tl;
    }
    // g: 16 outputs per thread
    float gacc[16];
    {
        int d0 = l4 * 16;
        #pragma unroll
        for (int j = 0; j < 16; j++) gacc[j] = gbs[d0 + j];
        #pragma unroll 8
        for (int c = 0; c < 64; c++) {
            float xv = xs[px * 64 + c];
            #pragma unroll
            for (int j = 0; j < 16; j++) gacc[j] = fmaf(xv, gws[c * 64 + d0 + j], gacc[j]);
        }
        #pragma unroll
        for (int j = 0; j < 16; j++) {
            float v = gacc[j];
            gacc[j] = v >= 0.f ? v : gas[d0 + j] * v;
        }
    }
    __syncthreads();           // all xs reads done; reuse xs for g staging
    {
        int d0 = l4 * 16;
        #pragma unroll
        for (int j = 0; j < 16; j++) xs[px * 64 + d0 + j] = gacc[j];
    }
    __syncthreads();
    // transpose-write: thread t -> (q = t>>6, ch = t&63); 16 k-values (mw 0..15)
    {
        int q = t >> 6, ch = t & 63;
        int mh = h >> 2, r = h & 3;
        __nv_bfloat16 hi[16], lo[16];
        #pragma unroll
        for (int mw = 0; mw < 16; mw++) {
            float v = xs[(mw * 4 + q) * 64 + ch];
            __nv_bfloat16 hb = __float2bfloat16(v);
            hi[mw] = hb;
            lo[mw] = __float2bfloat16(v - __bfloat162float(hb));
        }
        int n = (r * 4 + q) * 64 + ch;
        uint4* dh = (uint4*)&d_Gt_h[b][n][mh * 16];
        uint4* dl = (uint4*)&d_Gt_l[b][n][mh * 16];
        dh[0] = ((uint4*)hi)[0]; dh[1] = ((uint4*)hi)[1];
        dl[0] = ((uint4*)lo)[0]; dl[1] = ((uint4*)lo)[1];
    }
}

// ---------------------------------------------------------------------------
// Kernel 2: phi = prelu(conv1x1(bilinear_down4(x))).
// ---------------------------------------------------------------------------
__global__ __launch_bounds__(256) void k_phi(
    const float* __restrict__ x,
    const float* __restrict__ pw, const float* __restrict__ pb, const float* __restrict__ pa)
{
    int b = blockIdx.x;
    int t = threadIdx.x;
    __shared__ float pws[64 * 32];
    __shared__ float pbs[32], pas[32];
    for (int i = t; i < 64 * 32; i += 256) pws[i] = pw[i];
    if (t < 32) { pbs[t] = pb[t]; pas[t] = pa[t]; }
    __syncthreads();
    int nh = t >> 4, nw = t & 15;
    const float* xb = x + (size_t)b * 4096 * 64;
    const float* r0 = xb + ((4 * nh + 1) * 64 + (4 * nw + 1)) * 64;
    const float* r1 = xb + ((4 * nh + 2) * 64 + (4 * nw + 1)) * 64;
    float acc[32];
    #pragma unroll
    for (int d = 0; d < 32; d++) acc[d] = pbs[d];
    for (int c = 0; c < 64; c++) {
        float xv = 0.25f * (r0[c] + r0[64 + c] + r1[c] + r1[64 + c]);
        #pragma unroll
        for (int d = 0; d < 32; d++) acc[d] = fmaf(xv, pws[c * 32 + d], acc[d]);
    }
    float* o = &d_phi[b][nh + 1][nw + 1][0];
    #pragma unroll
    for (int d = 0; d < 32; d++) { float v = acc[d]; o[d] = v >= 0.f ? v : pas[d] * v; }
}

// ---------------------------------------------------------------------------
// Kernel 3: per-n patch L2 norm; write phin[n][k] bf16 hi/lo (K-major).
// ---------------------------------------------------------------------------
__global__ __launch_bounds__(256) void k_phin()
{
    int gwid = (blockIdx.x * 256 + threadIdx.x) >> 5;
    int lane = threadIdx.x & 31;
    if (gwid >= NB * 256) return;
    int b = gwid >> 8, n = gwid & 255;
    int nh = n >> 4, nw = n & 15;
    float v[9], ss = 0.f;
    #pragma unroll
    for (int i = 0; i < 9; i++) {
        v[i] = d_phi[b][nh + i / 3][nw + i % 3][lane];
        ss = fmaf(v[i], v[i], ss);
    }
    #pragma unroll
    for (int o = 16; o > 0; o >>= 1) ss += __shfl_xor_sync(0xffffffffu, ss, o);
    float rn = 1.0f / fmaxf(sqrtf(ss), 1e-6f);
    #pragma unroll
    for (int i = 0; i < 9; i++) {
        float u = v[i] * rn;
        __nv_bfloat16 hb = __float2bfloat16(u);
        d_phin_h[b][n][i * 32 + lane] = hb;
        d_phin_l[b][n][i * 32 + lane] = __float2bfloat16(u - __bfloat162float(hb));
    }
}

// ---------------------------------------------------------------------------
// Kernel 4: scores GEMM via mma.sync bf16 hi/lo + fused softmax(*10).
// Block: 64 m (one image row) x 256 n. 8 warps (2m x 4n), warp tile 32x64.
// K = 288 = 9 chunks of 32 (one (p,q) patch shift per chunk).
// ---------------------------------------------------------------------------
#define KS_AH 0
#define KS_AL 4096
#define KS_BH 8192
#define KS_BL 24576

__global__ __launch_bounds__(256) void k_scores_mma()
{
    __shared__ __align__(16) char sm[40960];
    int t = threadIdx.x, lane = t & 31, wid = t >> 5;
    int b = blockIdx.y, h = blockIdx.x, m0 = h << 6;
    int wm = wid >> 2, wn = wid & 3;
    uint32_t sbase = smem_to_u32(sm);

    float acc[2][8][4];
    #pragma unroll
    for (int i = 0; i < 2; i++)
        #pragma unroll
        for (int j = 0; j < 8; j++)
            #pragma unroll
            for (int k = 0; k < 4; k++) acc[i][j][k] = 0.f;

    int arow = t >> 2, aseg = t & 3;
    for (int pq = 0; pq < 9; pq++) {
        int p = pq / 3, q = pq - 3 * p;
        if (pq) __syncthreads();
        // A tile: 64 rows x 32 bf16 (hi/lo) patch gather
        {
            int so = SW64(arow, aseg * 16);
            *(uint4*)(sm + KS_AH + so) = *(const uint4*)&d_th_h[b][h + p][arow + q][aseg * 8];
            *(uint4*)(sm + KS_AL + so) = *(const uint4*)&d_th_l[b][h + p][arow + q][aseg * 8];
        }
        // B tile: 256 rows x 32 bf16 (hi/lo)
        #pragma unroll
        for (int i = 0; i < 4; i++) {
            int idx = t + (i << 8);
            int row = idx >> 2, seg = idx & 3;
            int so = SW64(row, seg * 16);
            int gk = pq * 32 + seg * 8;
            *(uint4*)(sm + KS_BH + so) = *(const uint4*)&d_phin_h[b][row][gk];
            *(uint4*)(sm + KS_BL + so) = *(const uint4*)&d_phin_l[b][row][gk];
        }
        __syncthreads();
        int lrow = lane & 15, lcol = (lane >> 4) << 4;
        #pragma unroll
        for (int ks = 0; ks < 2; ks++) {
            int colo = ks * 32 + lcol;
            uint32_t ah[2][4], al[2][4], bh[8][2], bl[8][2];
            #pragma unroll
            for (int mf = 0; mf < 2; mf++) {
                int rw = wm * 32 + mf * 16 + lrow;
                uint32_t addr = sbase + SW64(rw, colo);
                ldsm_x4(ah[mf], addr + KS_AH);
                ldsm_x4(al[mf], addr + KS_AL);
            }
            #pragma unroll
            for (int ng = 0; ng < 4; ng++) {
                int rw = wn * 64 + ng * 16 + lrow;
                uint32_t addr = sbase + SW64(rw, colo);
                uint32_t r4[4];
                ldsm_x4(r4, addr + KS_BH);
                bh[ng * 2][0] = r4[0]; bh[ng * 2][1] = r4[2];
                bh[ng * 2 + 1][0] = r4[1]; bh[ng * 2 + 1][1] = r4[3];
                ldsm_x4(r4, addr + KS_BL);
                bl[ng * 2][0] = r4[0]; bl[ng * 2][1] = r4[2];
                bl[ng * 2 + 1][0] = r4[1]; bl[ng * 2 + 1][1] = r4[3];
            }
            #pragma unroll
            for (int mf = 0; mf < 2; mf++)
                #pragma unroll
                for (int nf = 0; nf < 8; nf++) {
                    mma_bf16(acc[mf][nf], ah[mf], bh[nf]);
                    mma_bf16(acc[mf][nf], ah[mf], bl[nf]);
                    mma_bf16(acc[mf][nf], al[mf], bh[nf]);
                }
        }
    }
    __syncthreads();

    // fused softmax over n=256 per row
    float* redm = (float*)sm;              // [64][4]
    float* reds = (float*)(sm + 1024);     // [64][4]
    int group = lane >> 2, tig = lane & 3;
    // pass 1: per-row max partials
    #pragma unroll
    for (int mf = 0; mf < 2; mf++)
        #pragma unroll
        for (int half = 0; half < 2; half++) {
            float m = -1e30f;
            #pragma unroll
            for (int nf = 0; nf < 8; nf++) {
                m = fmaxf(m, acc[mf][nf][half * 2 + 0]);
                m = fmaxf(m, acc[mf][nf][half * 2 + 1]);
            }
            m = fmaxf(m, __shfl_xor_sync(0xffffffffu, m, 1));
            m = fmaxf(m, __shfl_xor_sync(0xffffffffu, m, 2));
            int row = wm * 32 + mf * 16 + half * 8 + group;
            if (tig == 0) redm[row * 4 + wn] = m;
        }
    __syncthreads();
    float invs[2][2];
    #pragma unroll
    for (int mf = 0; mf < 2; mf++)
        #pragma unroll
        for (int half = 0; half < 2; half++) {
            int row = wm * 32 + mf * 16 + half * 8 + group;
            float mx = fmaxf(fmaxf(redm[row * 4], redm[row * 4 + 1]),
                             fmaxf(redm[row * 4 + 2], redm[row * 4 + 3]));
            float s = 0.f;
            #pragma unroll
            for (int nf = 0; nf < 8; nf++) {
                float e0 = __expf(10.0f * (acc[mf][nf][half * 2 + 0] - mx));
                float e1 = __expf(10.0f * (acc[mf][nf][half * 2 + 1] - mx));
                acc[mf][nf][half * 2 + 0] = e0;
                acc[mf][nf][half * 2 + 1] = e1;
                s += e0 + e1;
            }
            s += __shfl_xor_sync(0xffffffffu, s, 1);
            s += __shfl_xor_sync(0xffffffffu, s, 2);
            if (tig == 0) reds[row * 4 + wn] = s;
        }
    __syncthreads();
    #pragma unroll
    for (int mf = 0; mf < 2; mf++)
        #pragma unroll
        for (int half = 0; half < 2; half++) {
            int row = wm * 32 + mf * 16 + half * 8 + group;
            float s = reds[row * 4] + reds[row * 4 + 1] + reds[row * 4 + 2] + reds[row * 4 + 3];
            invs[mf][half] = 1.0f / s;
        }
    #pragma unroll
    for (int mf = 0; mf < 2; mf++)
        #pragma unroll
        for (int half = 0; half < 2; half++) {
            int row = wm * 32 + mf * 16 + half * 8 + group;
            float inv = invs[mf][half];
            float* orow = &d_attn[b][m0 + row][0];
            #pragma unroll
            for (int nf = 0; nf < 8; nf++) {
                float2 v;
                v.x = acc[mf][nf][half * 2 + 0] * inv;
                v.y = acc[mf][nf][half * 2 + 1] * inv;
                *(float2*)&orow[wn * 64 + nf * 8 + tig * 2] = v;
            }
        }
}

// ---------------------------------------------------------------------------
// Kernel 5: A' 9-tap shifted accumulation of attn -> bf16 hi/lo split.
// ---------------------------------------------------------------------------
__global__ __launch_bounds__(256) void k_aprime()
{
    int idx = blockIdx.x * 256 + threadIdx.x;   // NB*4096*256 total
    int n = idx & 255;
    int m = (idx >> 8) & 4095;
    int b = idx >> 20;
    int a = m >> 6, bb = m & 63, mh = n >> 4, mw = n & 15;
    float s = 0.f;
    #pragma unroll
    for (int di = -1; di <= 1; di++) {
        int a2 = a - di, mh2 = mh - di;
        if ((unsigned)a2 < 64u && (unsigned)mh2 < 16u) {
            #pragma unroll
            for (int dj = -1; dj <= 1; dj++) {
                int b2 = bb - dj, mw2 = mw - dj;
                if ((unsigned)b2 < 64u && (unsigned)mw2 < 16u)
                    s += d_attn[b][a2 * 64 + b2][mh2 * 16 + mw2];
            }
        }
    }
    __nv_bfloat16 hb = __float2bfloat16(s);
    d_Ap_h[b][m][n] = hb;
    d_Ap_l[b][m][n] = __float2bfloat16(s - __bfloat162float(hb));
}

// ---------------------------------------------------------------------------
// Kernel 6: final GEMM via mma.sync bf16 hi/lo split.
// Per CTA: D[128m x 128n] = Ap[128 x 256k] @ Gt[128n x 256k]^T.
// ---------------------------------------------------------------------------
#define KF_RS   80                    // padded row stride (64B data + 16B pad)
#define KF_AH   0
#define KF_AL   10240
#define KF_BH   20480
#define KF_BL   30720

__global__ __launch_bounds__(256) void k_final_mma(float* __restrict__ out)
{
    __shared__ __align__(16) char sm[40960];
    int t = threadIdx.x, lane = t & 31, wid = t >> 5;
    int b = blockIdx.z, m0 = blockIdx.y << 7, n0 = blockIdx.x << 7;
    int wm = wid >> 1, wn = wid & 1;
    uint32_t sbase = smem_to_u32(sm);

    float acc[2][8][4];
    #pragma unroll
    for (int i = 0; i < 2; i++)
        #pragma unroll
        for (int j = 0; j < 8; j++)
            #pragma unroll
            for (int k = 0; k < 4; k++) acc[i][j][k] = 0.f;

    for (int kc = 0; kc < 8; kc++) {
        int k0 = kc << 5;
        if (kc) __syncthreads();
        #pragma unroll
        for (int i = 0; i < 2; i++) {
            int idx = t + (i << 8);        // 0..511
            int row = idx >> 2, seg = idx & 3;
            int so = row * KF_RS + seg * 16;
            int gk = k0 + seg * 8;
            *(uint4*)(sm + KF_AH + so) = *(const uint4*)&d_Ap_h[b][m0 + row][gk];
            *(uint4*)(sm + KF_AL + so) = *(const uint4*)&d_Ap_l[b][m0 + row][gk];
            *(uint4*)(sm + KF_BH + so) = *(const uint4*)&d_Gt_h[b][n0 + row][gk];
            *(uint4*)(sm + KF_BL + so) = *(const uint4*)&d_Gt_l[b][n0 + row][gk];
        }
        __syncthreads();
        int lrow = lane & 15, lcol = (lane >> 4) << 4;
        #pragma unroll
        for (int ks = 0; ks < 2; ks++) {
            int colo = ks * 32 + lcol;
            uint32_t ah[2][4], al[2][4], bh[8][2], bl[8][2];
            #pragma unroll
            for (int mf = 0; mf < 2; mf++) {
                uint32_t addr = sbase + (wm * 32 + mf * 16 + lrow) * KF_RS + colo;
                ldsm_x4(ah[mf], addr + KF_AH);
                ldsm_x4(al[mf], addr + KF_AL);
            }
            #pragma unroll
            for (int ng = 0; ng < 4; ng++) {
                uint32_t addr = sbase + (wn * 64 + ng * 16 + lrow) * KF_RS + colo;
                uint32_t r4[4];
                ldsm_x4(r4, addr + KF_BH);
                bh[ng * 2][0] = r4[0]; bh[ng * 2][1] = r4[2];
                bh[ng * 2 + 1][0] = r4[1]; bh[ng * 2 + 1][1] = r4[3];
                ldsm_x4(r4, addr + KF_BL);
                bl[ng * 2][0] = r4[0]; bl[ng * 2][1] = r4[2];
                bl[ng * 2 + 1][0] = r4[1]; bl[ng * 2 + 1][1] = r4[3];
            }
            #pragma unroll
            for (int mf = 0; mf < 2; mf++)
                #pragma unroll
                for (int nf = 0; nf < 8; nf++) {
                    mma_bf16(acc[mf][nf], ah[mf], bh[nf]);
                    mma_bf16(acc[mf][nf], ah[mf], bl[nf]);
                    mma_bf16(acc[mf][nf], al[mf], bh[nf]);
                }
        }
    }

    // epilogue: scatter with /6
    const float inv6 = 1.0f / 6.0f;
    int group = lane >> 2, tig = lane & 3;
    float* ob = out + (size_t)b * 4194304;
    #pragma unroll
    for (int mf = 0; mf < 2; mf++) {
        #pragma unroll
        for (int nf = 0; nf < 8; nf++) {
            int n = n0 + wn * 64 + nf * 8 + tig * 2;
            int r = n >> 8, q = (n >> 6) & 3, co = n & 63;
            #pragma unroll
            for (int half = 0; half < 2; half++) {
                int m = m0 + wm * 32 + mf * 16 + group + half * 8;
                int a = m >> 6, bw = m & 63;
                float2 v;
                v.x = acc[mf][nf][half * 2 + 0] * inv6;
                v.y = acc[mf][nf][half * 2 + 1] * inv6;
                *(float2*)&ob[((size_t)((a * 4 + r) * 256 + bw * 4 + q)) * 64 + co] = v;
            }
        }
    }
}

// ---------------------------------------------------------------------------
extern "C" void kernel_launch(void* const* d_in, const int* in_sizes, int n_in,
                              void* d_out, int out_size)
{
    const float* x  = (const float*)d_in[0];
    const float* tw = (const float*)d_in[1];
    const float* tb = (const float*)d_in[2];
    const float* ta = (const float*)d_in[3];
    const float* pw = (const float*)d_in[4];
    const float* pb = (const float*)d_in[5];
    const float* pa = (const float*)d_in[6];
    const float* gw = (const float*)d_in[7];
    const float* gb = (const float*)d_in[8];
    const float* ga = (const float*)d_in[9];
    float* out = (float*)d_out;

    k_theta_g<<<NB * 64, 256>>>(x, tw, tb, ta, gw, gb, ga);
    k_phi<<<NB, 256>>>(x, pw, pb, pa);
    k_phin<<<256, 256>>>();
    k_scores_mma<<<dim3(64, NB), 256>>>();
    k_aprime<<<NB * 4096, 256>>>();
    k_final_mma<<<dim3(8, 32, NB), 256>>>(out);
}

// round 14
// speedup vs baseline: 1.4161x; 1.4161x over previous
#include <cuda_runtime.h>
#include <cuda_bf16.h>
#include <math.h>
#include <stdint.h>

// ---------------------------------------------------------------------------
// CrossScaleNonLocalAttention  (B=8, H=W=64, C=64, CI=32, SCALE=4, PATCH=3)
//
// R12: mma.sync bf16 hi/lo split GEMMs with 2-stage cp.async pipelines, now
// entirely in STATIC shared memory (K-chunk 16, 32B swizzled rows) — no
// cudaFuncSetAttribute, no dynamic smem (suspected container-killer in
// R10/R11's 80KB-dynamic variant).
// ---------------------------------------------------------------------------

#define NB 8

__device__ float d_phi[NB][18][18][32];             // zero-padded border
__device__ float d_attn[NB][4096][256];
__device__ __nv_bfloat16 d_th_h[NB][66][66][32];    // theta hi/lo, padded
__device__ __nv_bfloat16 d_th_l[NB][66][66][32];
__device__ __nv_bfloat16 d_phin_h[NB][256][288];    // phin[n][k] hi/lo
__device__ __nv_bfloat16 d_phin_l[NB][256][288];
__device__ __nv_bfloat16 d_Ap_h[NB][4096][256];     // A' hi/lo split
__device__ __nv_bfloat16 d_Ap_l[NB][4096][256];
__device__ __nv_bfloat16 d_Gt_h[NB][1024][256];     // Gt[n][k] hi/lo split
__device__ __nv_bfloat16 d_Gt_l[NB][1024][256];

// ---- mma.sync / cp.async helpers -------------------------------------------
__device__ __forceinline__ uint32_t smem_to_u32(const void* p) {
    uint32_t a;
    asm("{ .reg .u64 tmp; cvta.to.shared.u64 tmp, %1; cvt.u32.u64 %0, tmp; }"
        : "=r"(a) : "l"(p));
    return a;
}
__device__ __forceinline__ void ldsm_x4(uint32_t* r, uint32_t addr) {
    asm volatile("ldmatrix.sync.aligned.m8n8.x4.shared.b16 {%0,%1,%2,%3}, [%4];"
                 : "=r"(r[0]), "=r"(r[1]), "=r"(r[2]), "=r"(r[3]) : "r"(addr));
}
__device__ __forceinline__ void mma_bf16(float* d, const uint32_t* a, const uint32_t* b) {
    asm volatile(
        "mma.sync.aligned.m16n8k16.row.col.f32.bf16.bf16.f32 "
        "{%0,%1,%2,%3}, {%4,%5,%6,%7}, {%8,%9}, {%0,%1,%2,%3};"
        : "+f"(d[0]), "+f"(d[1]), "+f"(d[2]), "+f"(d[3])
        : "r"(a[0]), "r"(a[1]), "r"(a[2]), "r"(a[3]), "r"(b[0]), "r"(b[1]));
}
__device__ __forceinline__ void cp16(uint32_t s, const void* g) {
    asm volatile("cp.async.cg.shared.global [%0], [%1], 16;" :: "r"(s), "l"(g) : "memory");
}
#define CP_COMMIT() asm volatile("cp.async.commit_group;" ::: "memory")
#define CP_WAIT1()  asm volatile("cp.async.wait_group 1;" ::: "memory")
#define CP_WAIT0()  asm volatile("cp.async.wait_group 0;" ::: "memory")
// conflict-free XOR swizzle for 32B rows of two 16B segments:
// 8-row window occupies slots {0,32,64,96,16,48,80,112} mod 128 -> no conflicts
#define SWZ32(row, seg) ((row) * 32 + ((((seg) ^ (((row) >> 2) & 1))) << 4))

// ---------------------------------------------------------------------------
// Kernel 1: theta (64->32) and g (64->64) 1x1 conv + PReLU, fused.
// theta stored bf16 hi/lo padded [66][66][32]; g transposed to Gt[n][k] hi/lo.
// ---------------------------------------------------------------------------
__global__ __launch_bounds__(256) void k_theta_g(
    const float* __restrict__ x,
    const float* __restrict__ tw, const float* __restrict__ tb, const float* __restrict__ ta,
    const float* __restrict__ gw, const float* __restrict__ gb, const float* __restrict__ ga)
{
    int b = blockIdx.x >> 6, h = blockIdx.x & 63;
    __shared__ float xs[64 * 64];
    __shared__ float tws[64 * 32];
    __shared__ float gws[64 * 64];
    __shared__ float tbs[32], tas[32], gbs[64], gas[64];
    int t = threadIdx.x;
    for (int i = t; i < 64 * 32; i += 256) tws[i] = tw[i];
    for (int i = t; i < 64 * 64; i += 256) gws[i] = gw[i];
    if (t < 32) { tbs[t] = tb[t]; tas[t] = ta[t]; }
    if (t < 64) { gbs[t] = gb[t]; gas[t] = ga[t]; }
    const float* xrow = x + ((size_t)(b * 4096 + h * 64)) * 64;
    for (int i = t * 4; i < 4096; i += 1024)
        *(float4*)&xs[i] = *(const float4*)&xrow[i];
    __syncthreads();

    int px = t >> 2, l4 = t & 3;
    // theta: 8 outputs per thread -> bf16 hi/lo
    {
        float acc[8];
        int d0 = l4 * 8;
        #pragma unroll
        for (int j = 0; j < 8; j++) acc[j] = tbs[d0 + j];
        #pragma unroll 8
        for (int c = 0; c < 64; c++) {
            float xv = xs[px * 64 + c];
            #pragma unroll
            for (int j = 0; j < 8; j++) acc[j] = fmaf(xv, tws[c * 32 + d0 + j], acc[j]);
        }
        __nv_bfloat16 th[8], tl[8];
        #pragma unroll
        for (int j = 0; j < 8; j++) {
            float v = acc[j];
            v = v >= 0.f ? v : tas[d0 + j] * v;
            __nv_bfloat16 hb = __float2bfloat16(v);
            th[j] = hb;
            tl[j] = __float2bfloat16(v - __bfloat162float(hb));
        }
        *(uint4*)&d_th_h[b][h + 1][px + 1][d0] = *(uint4*)th;
        *(uint4*)&d_th_l[b][h + 1][px + 1][d0] = *(uint4*)tl;
    }
    // g: 16 outputs per thread
    float gacc[16];
    {
        int d0 = l4 * 16;
        #pragma unroll
        for (int j = 0; j < 16; j++) gacc[j] = gbs[d0 + j];
        #pragma unroll 8
        for (int c = 0; c < 64; c++) {
            float xv = xs[px * 64 + c];
            #pragma unroll
            for (int j = 0; j < 16; j++) gacc[j] = fmaf(xv, gws[c * 64 + d0 + j], gacc[j]);
        }
        #pragma unroll
        for (int j = 0; j < 16; j++) {
            float v = gacc[j];
            gacc[j] = v >= 0.f ? v : gas[d0 + j] * v;
        }
    }
    __syncthreads();           // all xs reads done; reuse xs for g staging
    {
        int d0 = l4 * 16;
        #pragma unroll
        for (int j = 0; j < 16; j++) xs[px * 64 + d0 + j] = gacc[j];
    }
    __syncthreads();
    // transpose-write: thread t -> (q = t>>6, ch = t&63); 16 k-values (mw 0..15)
    {
        int q = t >> 6, ch = t & 63;
        int mh = h >> 2, r = h & 3;
        __nv_bfloat16 hi[16], lo[16];
        #pragma unroll
        for (int mw = 0; mw < 16; mw++) {
            float v = xs[(mw * 4 + q) * 64 + ch];
            __nv_bfloat16 hb = __float2bfloat16(v);
            hi[mw] = hb;
            lo[mw] = __float2bfloat16(v - __bfloat162float(hb));
        }
        int n = (r * 4 + q) * 64 + ch;
        uint4* dh = (uint4*)&d_Gt_h[b][n][mh * 16];
        uint4* dl = (uint4*)&d_Gt_l[b][n][mh * 16];
        dh[0] = ((uint4*)hi)[0]; dh[1] = ((uint4*)hi)[1];
        dl[0] = ((uint4*)lo)[0]; dl[1] = ((uint4*)lo)[1];
    }
}

// ---------------------------------------------------------------------------
// Kernel 2: phi = prelu(conv1x1(bilinear_down4(x))).
// ---------------------------------------------------------------------------
__global__ __launch_bounds__(256) void k_phi(
    const float* __restrict__ x,
    const float* __restrict__ pw, const float* __restrict__ pb, const float* __restrict__ pa)
{
    int b = blockIdx.x;
    int t = threadIdx.x;
    __shared__ float pws[64 * 32];
    __shared__ float pbs[32], pas[32];
    for (int i = t; i < 64 * 32; i += 256) pws[i] = pw[i];
    if (t < 32) { pbs[t] = pb[t]; pas[t] = pa[t]; }
    __syncthreads();
    int nh = t >> 4, nw = t & 15;
    const float* xb = x + (size_t)b * 4096 * 64;
    const float* r0 = xb + ((4 * nh + 1) * 64 + (4 * nw + 1)) * 64;
    const float* r1 = xb + ((4 * nh + 2) * 64 + (4 * nw + 1)) * 64;
    float acc[32];
    #pragma unroll
    for (int d = 0; d < 32; d++) acc[d] = pbs[d];
    for (int c = 0; c < 64; c++) {
        float xv = 0.25f * (r0[c] + r0[64 + c] + r1[c] + r1[64 + c]);
        #pragma unroll
        for (int d = 0; d < 32; d++) acc[d] = fmaf(xv, pws[c * 32 + d], acc[d]);
    }
    float* o = &d_phi[b][nh + 1][nw + 1][0];
    #pragma unroll
    for (int d = 0; d < 32; d++) { float v = acc[d]; o[d] = v >= 0.f ? v : pas[d] * v; }
}

// ---------------------------------------------------------------------------
// Kernel 3: per-n patch L2 norm; write phin[n][k] bf16 hi/lo (K-major).
// ---------------------------------------------------------------------------
__global__ __launch_bounds__(256) void k_phin()
{
    int gwid = (blockIdx.x * 256 + threadIdx.x) >> 5;
    int lane = threadIdx.x & 31;
    if (gwid >= NB * 256) return;
    int b = gwid >> 8, n = gwid & 255;
    int nh = n >> 4, nw = n & 15;
    float v[9], ss = 0.f;
    #pragma unroll
    for (int i = 0; i < 9; i++) {
        v[i] = d_phi[b][nh + i / 3][nw + i % 3][lane];
        ss = fmaf(v[i], v[i], ss);
    }
    #pragma unroll
    for (int o = 16; o > 0; o >>= 1) ss += __shfl_xor_sync(0xffffffffu, ss, o);
    float rn = 1.0f / fmaxf(sqrtf(ss), 1e-6f);
    #pragma unroll
    for (int i = 0; i < 9; i++) {
        float u = v[i] * rn;
        __nv_bfloat16 hb = __float2bfloat16(u);
        d_phin_h[b][n][i * 32 + lane] = hb;
        d_phin_l[b][n][i * 32 + lane] = __float2bfloat16(u - __bfloat162float(hb));
    }
}

// ---------------------------------------------------------------------------
// Kernel 4: scores GEMM via mma.sync bf16 hi/lo + fused softmax(*10).
// 64 m (one image row) x 256 n per block; 8 warps (2m x 4n), warp tile 32x64.
// K = 288 = 18 chunks of 16; 2-stage cp.async pipeline, STATIC smem.
// Stage: AH 0 (2K) AL 2K BH 4K (8K) BL 12K; stage stride 20480; 2 stages.
// ---------------------------------------------------------------------------
#define KS_AH 0
#define KS_AL 2048
#define KS_BH 4096
#define KS_BL 12288
#define KS_STG 20480

__global__ __launch_bounds__(256) void k_scores_mma()
{
    __shared__ __align__(16) char sm[2 * KS_STG];
    __shared__ float redm[64 * 4];
    __shared__ float reds[64 * 4];
    int t = threadIdx.x, lane = t & 31, wid = t >> 5;
    int b = blockIdx.y, h = blockIdx.x, m0 = h << 6;
    int wm = wid >> 2, wn = wid & 3;
    uint32_t sbase = smem_to_u32(sm);

    float acc[2][8][4];
    #pragma unroll
    for (int i = 0; i < 2; i++)
        #pragma unroll
        for (int j = 0; j < 8; j++)
            #pragma unroll
            for (int k = 0; k < 4; k++) acc[i][j][k] = 0.f;

    auto load_chunk = [&](int c, int stg) {
        int pq = c >> 1, kh = c & 1;
        int p = pq / 3, q = pq - 3 * p;
        uint32_t s0 = sbase + stg * KS_STG;
        // A: 64 rows x 2 segs = 128 segments -> threads 0..127
        if (t < 128) {
            int row = t >> 1, seg = t & 1;
            uint32_t so = SWZ32(row, seg);
            int ck = kh * 16 + seg * 8;
            cp16(s0 + KS_AH + so, &d_th_h[b][h + p][row + q][ck]);
            cp16(s0 + KS_AL + so, &d_th_l[b][h + p][row + q][ck]);
        }
        // B: 256 rows x 2 segs = 512 segments -> 2 per thread
        #pragma unroll
        for (int i = 0; i < 2; i++) {
            int idx = t + (i << 8);
            int row = idx >> 1, seg = idx & 1;
            uint32_t so = SWZ32(row, seg);
            int gk = pq * 32 + kh * 16 + seg * 8;
            cp16(s0 + KS_BH + so, &d_phin_h[b][row][gk]);
            cp16(s0 + KS_BL + so, &d_phin_l[b][row][gk]);
        }
    };

    load_chunk(0, 0);
    CP_COMMIT();
    for (int c = 0; c < 18; c++) {
        if (c < 17) { load_chunk(c + 1, (c + 1) & 1); CP_COMMIT(); CP_WAIT1(); }
        else        { CP_WAIT0(); }
        __syncthreads();
        uint32_t s0 = sbase + (c & 1) * KS_STG;
        int lrow = lane & 15, lseg = lane >> 4;
        uint32_t ah[2][4], al[2][4], bh[8][2], bl[8][2];
        #pragma unroll
        for (int mf = 0; mf < 2; mf++) {
            int rw = wm * 32 + mf * 16 + lrow;
            uint32_t addr = s0 + SWZ32(rw, lseg);
            ldsm_x4(ah[mf], addr + KS_AH);
            ldsm_x4(al[mf], addr + KS_AL);
        }
        #pragma unroll
        for (int ng = 0; ng < 4; ng++) {
            int rw = wn * 64 + ng * 16 + lrow;
            uint32_t addr = s0 + SWZ32(rw, lseg);
            uint32_t r4[4];
            ldsm_x4(r4, addr + KS_BH);
            bh[ng * 2][0] = r4[0]; bh[ng * 2][1] = r4[2];
            bh[ng * 2 + 1][0] = r4[1]; bh[ng * 2 + 1][1] = r4[3];
            ldsm_x4(r4, addr + KS_BL);
            bl[ng * 2][0] = r4[0]; bl[ng * 2][1] = r4[2];
            bl[ng * 2 + 1][0] = r4[1]; bl[ng * 2 + 1][1] = r4[3];
        }
        #pragma unroll
        for (int mf = 0; mf < 2; mf++)
            #pragma unroll
            for (int nf = 0; nf < 8; nf++) {
                mma_bf16(acc[mf][nf], ah[mf], bh[nf]);
                mma_bf16(acc[mf][nf], ah[mf], bl[nf]);
                mma_bf16(acc[mf][nf], al[mf], bh[nf]);
            }
        __syncthreads();
    }

    // fused softmax over n=256 per row
    int group = lane >> 2, tig = lane & 3;
    #pragma unroll
    for (int mf = 0; mf < 2; mf++)
        #pragma unroll
        for (int half = 0; half < 2; half++) {
            float m = -1e30f;
            #pragma unroll
            for (int nf = 0; nf < 8; nf++) {
                m = fmaxf(m, acc[mf][nf][half * 2 + 0]);
                m = fmaxf(m, acc[mf][nf][half * 2 + 1]);
            }
            m = fmaxf(m, __shfl_xor_sync(0xffffffffu, m, 1));
            m = fmaxf(m, __shfl_xor_sync(0xffffffffu, m, 2));
            int row = wm * 32 + mf * 16 + half * 8 + group;
            if (tig == 0) redm[row * 4 + wn] = m;
        }
    __syncthreads();
    float invs[2][2];
    #pragma unroll
    for (int mf = 0; mf < 2; mf++)
        #pragma unroll
        for (int half = 0; half < 2; half++) {
            int row = wm * 32 + mf * 16 + half * 8 + group;
            float mx = fmaxf(fmaxf(redm[row * 4], redm[row * 4 + 1]),
                             fmaxf(redm[row * 4 + 2], redm[row * 4 + 3]));
            float s = 0.f;
            #pragma unroll
            for (int nf = 0; nf < 8; nf++) {
                float e0 = __expf(10.0f * (acc[mf][nf][half * 2 + 0] - mx));
                float e1 = __expf(10.0f * (acc[mf][nf][half * 2 + 1] - mx));
                acc[mf][nf][half * 2 + 0] = e0;
                acc[mf][nf][half * 2 + 1] = e1;
                s += e0 + e1;
            }
            s += __shfl_xor_sync(0xffffffffu, s, 1);
            s += __shfl_xor_sync(0xffffffffu, s, 2);
            if (tig == 0) reds[row * 4 + wn] = s;
        }
    __syncthreads();
    #pragma unroll
    for (int mf = 0; mf < 2; mf++)
        #pragma unroll
        for (int half = 0; half < 2; half++) {
            int row = wm * 32 + mf * 16 + half * 8 + group;
            float s = reds[row * 4] + reds[row * 4 + 1] + reds[row * 4 + 2] + reds[row * 4 + 3];
            invs[mf][half] = 1.0f / s;
        }
    #pragma unroll
    for (int mf = 0; mf < 2; mf++)
        #pragma unroll
        for (int half = 0; half < 2; half++) {
            int row = wm * 32 + mf * 16 + half * 8 + group;
            float inv = invs[mf][half];
            float* orow = &d_attn[b][m0 + row][0];
            #pragma unroll
            for (int nf = 0; nf < 8; nf++) {
                float2 v;
                v.x = acc[mf][nf][half * 2 + 0] * inv;
                v.y = acc[mf][nf][half * 2 + 1] * inv;
                *(float2*)&orow[wn * 64 + nf * 8 + tig * 2] = v;
            }
        }
}

// ---------------------------------------------------------------------------
// Kernel 5: A' 9-tap shifted accumulation of attn -> bf16 hi/lo split.
// ---------------------------------------------------------------------------
__global__ __launch_bounds__(256) void k_aprime()
{
    int idx = blockIdx.x * 256 + threadIdx.x;   // NB*4096*256 total
    int n = idx & 255;
    int m = (idx >> 8) & 4095;
    int b = idx >> 20;
    int a = m >> 6, bb = m & 63, mh = n >> 4, mw = n & 15;
    float s = 0.f;
    #pragma unroll
    for (int di = -1; di <= 1; di++) {
        int a2 = a - di, mh2 = mh - di;
        if ((unsigned)a2 < 64u && (unsigned)mh2 < 16u) {
            #pragma unroll
            for (int dj = -1; dj <= 1; dj++) {
                int b2 = bb - dj, mw2 = mw - dj;
                if ((unsigned)b2 < 64u && (unsigned)mw2 < 16u)
                    s += d_attn[b][a2 * 64 + b2][mh2 * 16 + mw2];
            }
        }
    }
    __nv_bfloat16 hb = __float2bfloat16(s);
    d_Ap_h[b][m][n] = hb;
    d_Ap_l[b][m][n] = __float2bfloat16(s - __bfloat162float(hb));
}

// ---------------------------------------------------------------------------
// Kernel 6: final GEMM via mma.sync bf16 hi/lo split, 2-stage cp.async,
// STATIC smem. Per CTA: D[128m x 128n] = Ap[128 x 256k] @ Gt[128n x 256k]^T.
// K = 256 = 16 chunks of 16. Stage: AH 0 AL 4K BH 8K BL 12K (32B rows);
// stage stride 16384; 2 stages = 32KB.
// ---------------------------------------------------------------------------
#define KF_AH   0
#define KF_AL   4096
#define KF_BH   8192
#define KF_BL   12288
#define KF_STG  16384

__global__ __launch_bounds__(256) void k_final_mma(float* __restrict__ out)
{
    __shared__ __align__(16) char sm[2 * KF_STG];
    int t = threadIdx.x, lane = t & 31, wid = t >> 5;
    int b = blockIdx.z, m0 = blockIdx.y << 7, n0 = blockIdx.x << 7;
    int wm = wid >> 1, wn = wid & 1;
    uint32_t sbase = smem_to_u32(sm);

    float acc[2][8][4];
    #pragma unroll
    for (int i = 0; i < 2; i++)
        #pragma unroll
        for (int j = 0; j < 8; j++)
            #pragma unroll
            for (int k = 0; k < 4; k++) acc[i][j][k] = 0.f;

    auto load_chunk = [&](int kc, int stg) {
        uint32_t s0 = sbase + stg * KF_STG;
        int k0 = kc << 4;
        // 128 rows x 2 segs = 256 segments per tile -> 1 per thread per tile
        int row = t >> 1, seg = t & 1;
        uint32_t so = SWZ32(row, seg);
        int gk = k0 + seg * 8;
        cp16(s0 + KF_AH + so, &d_Ap_h[b][m0 + row][gk]);
        cp16(s0 + KF_AL + so, &d_Ap_l[b][m0 + row][gk]);
        cp16(s0 + KF_BH + so, &d_Gt_h[b][n0 + row][gk]);
        cp16(s0 + KF_BL + so, &d_Gt_l[b][n0 + row][gk]);
    };

    load_chunk(0, 0);
    CP_COMMIT();
    for (int kc = 0; kc < 16; kc++) {
        if (kc < 15) { load_chunk(kc + 1, (kc + 1) & 1); CP_COMMIT(); CP_WAIT1(); }
        else         { CP_WAIT0(); }
        __syncthreads();
        uint32_t s0 = sbase + (kc & 1) * KF_STG;
        int lrow = lane & 15, lseg = lane >> 4;
        uint32_t ah[2][4], al[2][4], bh[8][2], bl[8][2];
        #pragma unroll
        for (int mf = 0; mf < 2; mf++) {
            int rw = wm * 32 + mf * 16 + lrow;
            uint32_t addr = s0 + SWZ32(rw, lseg);
            ldsm_x4(ah[mf], addr + KF_AH);
            ldsm_x4(al[mf], addr + KF_AL);
        }
        #pragma unroll
        for (int ng = 0; ng < 4; ng++) {
            int rw = wn * 64 + ng * 16 + lrow;
            uint32_t addr = s0 + SWZ32(rw, lseg);
            uint32_t r4[4];
            ldsm_x4(r4, addr + KF_BH);
            bh[ng * 2][0] = r4[0]; bh[ng * 2][1] = r4[2];
            bh[ng * 2 + 1][0] = r4[1]; bh[ng * 2 + 1][1] = r4[3];
            ldsm_x4(r4, addr + KF_BL);
            bl[ng * 2][0] = r4[0]; bl[ng * 2][1] = r4[2];
            bl[ng * 2 + 1][0] = r4[1]; bl[ng * 2 + 1][1] = r4[3];
        }
        #pragma unroll
        for (int mf = 0; mf < 2; mf++)
            #pragma unroll
            for (int nf = 0; nf < 8; nf++) {
                mma_bf16(acc[mf][nf], ah[mf], bh[nf]);
                mma_bf16(acc[mf][nf], ah[mf], bl[nf]);
                mma_bf16(acc[mf][nf], al[mf], bh[nf]);
            }
        __syncthreads();
    }

    // epilogue: scatter with /6
    const float inv6 = 1.0f / 6.0f;
    int group = lane >> 2, tig = lane & 3;
    float* ob = out + (size_t)b * 4194304;
    #pragma unroll
    for (int mf = 0; mf < 2; mf++) {
        #pragma unroll
        for (int nf = 0; nf < 8; nf++) {
            int n = n0 + wn * 64 + nf * 8 + tig * 2;
            int r = n >> 8, q = (n >> 6) & 3, co = n & 63;
            #pragma unroll
            for (int half = 0; half < 2; half++) {
                int m = m0 + wm * 32 + mf * 16 + group + half * 8;
                int a = m >> 6, bw = m & 63;
                float2 v;
                v.x = acc[mf][nf][half * 2 + 0] * inv6;
                v.y = acc[mf][nf][half * 2 + 1] * inv6;
                *(float2*)&ob[((size_t)((a * 4 + r) * 256 + bw * 4 + q)) * 64 + co] = v;
            }
        }
    }
}

// ---------------------------------------------------------------------------
extern "C" void kernel_launch(void* const* d_in, const int* in_sizes, int n_in,
                              void* d_out, int out_size)
{
    const float* x  = (const float*)d_in[0];
    const float* tw = (const float*)d_in[1];
    const float* tb = (const float*)d_in[2];
    const float* ta = (const float*)d_in[3];
    const float* pw = (const float*)d_in[4];
    const float* pb = (const float*)d_in[5];
    const float* pa = (const float*)d_in[6];
    const float* gw = (const float*)d_in[7];
    const float* gb = (const float*)d_in[8];
    const float* ga = (const float*)d_in[9];
    float* out = (float*)d_out;

    k_theta_g<<<NB * 64, 256>>>(x, tw, tb, ta, gw, gb, ga);
    k_phi<<<NB, 256>>>(x, pw, pb, pa);
    k_phin<<<256, 256>>>();
    k_scores_mma<<<dim3(64, NB), 256>>>();
    k_aprime<<<NB * 4096, 256>>>();
    k_final_mma<<<dim3(8, 32, NB), 256>>>(out);
}